// round 13
// baseline (speedup 1.0000x reference)
#include <cuda_runtime.h>
#include <cuda_bf16.h>

typedef unsigned int       u32;
typedef unsigned long long u64;

#define BATCH 32
#define TQ    512
#define TK    2048
#define DIM   512

// ---------------------------------------------------------------------------
// Scratch. 2-section split storage: row = [hi(K) | lo(K)].
// Product = hi*hi + lo*hi + hi*lo (fp32 minus O(2^-18) lo*lo term)
// ---------------------------------------------------------------------------
__device__ __nv_bfloat16 g_Q2 [(size_t)BATCH * TQ  * 2 * DIM];  //  34 MB
__device__ __nv_bfloat16 g_E2 [(size_t)BATCH * TK  * 2 * DIM];  // 134 MB
__device__ float         g_S  [(size_t)BATCH * TQ  * TK];       // 134 MB
__device__ __nv_bfloat16 g_ET2[(size_t)BATCH * DIM * 2 * TK];   // 134 MB
__device__ float2        g_stat[(size_t)BATCH * TQ * (TK / 128)]; // 2 MB
__device__ float2        g_row [(size_t)BATCH * TQ];              // 128 KB

// ---------------------------------------------------------------------------
// Baseline-PTX tensor-core helpers
// ---------------------------------------------------------------------------
__device__ __forceinline__ u32 smem_u32(const void* p) {
    u32 a;
    asm("{ .reg .u64 t; cvta.to.shared.u64 t, %1; cvt.u32.u64 %0, t; }"
        : "=r"(a) : "l"(p));
    return a;
}

__device__ __forceinline__ void ldmatrix_x4(u32& r0, u32& r1, u32& r2, u32& r3,
                                            u32 addr) {
    asm volatile("ldmatrix.sync.aligned.m8n8.x4.shared.b16 {%0,%1,%2,%3}, [%4];"
                 : "=r"(r0), "=r"(r1), "=r"(r2), "=r"(r3) : "r"(addr));
}

__device__ __forceinline__ void mma_16816(float* c, const u32* a, const u32* b) {
    asm volatile(
        "mma.sync.aligned.m16n8k16.row.col.f32.bf16.bf16.f32 "
        "{%0,%1,%2,%3}, {%4,%5,%6,%7}, {%8,%9}, {%0,%1,%2,%3};"
        : "+f"(c[0]), "+f"(c[1]), "+f"(c[2]), "+f"(c[3])
        : "r"(a[0]), "r"(a[1]), "r"(a[2]), "r"(a[3]), "r"(b[0]), "r"(b[1]));
}

#define CP_ASYNC_16(saddr, gptr) \
    asm volatile("cp.async.cg.shared.global [%0], [%1], 16;" \
                 :: "r"(saddr), "l"(gptr) : "memory")
#define CP_COMMIT() asm volatile("cp.async.commit_group;" ::: "memory")
#define CP_WAIT(n)  asm volatile("cp.async.wait_group %0;" :: "n"(n) : "memory")

// ===========================================================================
// GEMM1 (chunk-major): S = Q @ E^T + per-tile softmax stats.
// Each 32-k chunk loads (A_hi|A_lo) and (B_hi|B_lo) once into 144B rows,
// then 6 steps: {hi,ks0},{hi,ks1},{lo_A,ks0},{lo_A,ks1},{lo_B,ks0},{lo_B,ks1}.
// CTA 128x128, 3-stage cp.async, 8 warps (32m x 64n warp tiles).
// ===========================================================================
#define STAGES     3
#define ROWB       144                       // 64 bf16 (hi32|lo32) + 16B pad
#define TILE_BYTES (128 * ROWB)
#define STAGE_BYTES (2 * TILE_BYTES)
#define GEMM_SMEM  (STAGES * STAGE_BYTES)    // 110592

__global__ void __launch_bounds__(256, 2)
gemm1_stats(const __nv_bfloat16* __restrict__ A, const __nv_bfloat16* __restrict__ B,
            float* __restrict__ C, float2* __restrict__ stat)
{
    extern __shared__ char smem[];
    const u32 smem_base = smem_u32(smem);

    constexpr int K   = DIM;
    constexpr int KT  = 2 * K;
    constexpr int NC  = K / 32;          // 16 chunks
    constexpr int N   = TK;

    const int tid = threadIdx.x;
    const int wid = tid >> 5;
    const int lid = tid & 31;
    const int wm  = wid & 3;
    const int wn  = wid >> 2;

    A += (long long)blockIdx.z * (TQ * (long long)KT);
    B += (long long)blockIdx.z * (TK * (long long)KT);
    C += (long long)blockIdx.z * ((long long)TQ * TK);
    const int m0 = blockIdx.y * 128;
    const int n0 = blockIdx.x * 128;

    // cp.async: q = 16B chunk in row (0-3 -> hi, 4-7 -> lo), r0 + 32i rows
    const int q  = tid & 7;
    const int r0 = tid >> 3;
    const int gcol = ((q < 4) ? 0 : K) + (q & 3) * 8;   // + c*32 at use

    const int a_off = (wm * 32 + (lid & 15)) * ROWB + ((lid >> 4) << 4);
    const int b_off = (wn * 64 + ((lid >> 4) << 3) + (lid & 7)) * ROWB +
                      (((lid >> 3) & 1) << 4);

    float acc[2][8][4];
#pragma unroll
    for (int mt = 0; mt < 2; mt++)
#pragma unroll
        for (int nt = 0; nt < 8; nt++)
#pragma unroll
            for (int j = 0; j < 4; j++) acc[mt][nt][j] = 0.0f;

    auto load_stage = [&](int s, int c) {
        const u32 sa = smem_base + s * STAGE_BYTES;
        const u32 sb = sa + TILE_BYTES;
        const __nv_bfloat16* Ap = A + (long long)(m0 + r0) * KT + gcol + c * 32;
        const __nv_bfloat16* Bp = B + (long long)(n0 + r0) * KT + gcol + c * 32;
#pragma unroll
        for (int i = 0; i < 4; i++) {
            CP_ASYNC_16(sa + (r0 + i * 32) * ROWB + q * 16, Ap + (long long)(i * 32) * KT);
            CP_ASYNC_16(sb + (r0 + i * 32) * ROWB + q * 16, Bp + (long long)(i * 32) * KT);
        }
    };

    load_stage(0, 0); CP_COMMIT();
    load_stage(1, 1); CP_COMMIT();

    // step -> smem byte offset within the 128B row data
    const int AOFF[6] = {0, 32, 64, 96, 0, 32};    // hi,hi,lo,lo,hi,hi
    const int BOFF[6] = {0, 32, 0, 32, 64, 96};    // hi,hi,hi,hi,lo,lo

    int sc = 0, sl = 2;
    for (int c = 0; c < NC; c++) {
        CP_WAIT(1);
        __syncthreads();

        if (c + 2 < NC) load_stage(sl, c + 2);
        CP_COMMIT();

        const u32 sa = smem_base + sc * STAGE_BYTES;
        const u32 sb = sa + TILE_BYTES;

        u32 ab[2][2][4];
        u32 bb[2][2][2];

        ldmatrix_x4(ab[0][0][0], ab[0][0][1], ab[0][0][2], ab[0][0][3],
                    sa + a_off + AOFF[0]);
        ldmatrix_x4(ab[0][1][0], ab[0][1][1], ab[0][1][2], ab[0][1][3],
                    sa + a_off + 16 * ROWB + AOFF[0]);
        ldmatrix_x4(bb[0][0][0], bb[0][0][1], bb[0][1][0], bb[0][1][1],
                    sb + b_off + BOFF[0]);

#pragma unroll
        for (int st = 0; st < 6; st++) {
            const int cb = st & 1;
#pragma unroll
            for (int bt = 0; bt < 4; bt++) {
                if (bt < 3) {
                    const int nb = (bt + 1) & 1;
                    ldmatrix_x4(bb[nb][0][0], bb[nb][0][1], bb[nb][1][0], bb[nb][1][1],
                                sb + b_off + (bt + 1) * 16 * ROWB + BOFF[st]);
                } else if (st < 5) {
                    const int na = (st + 1) & 1;
                    ldmatrix_x4(ab[na][0][0], ab[na][0][1], ab[na][0][2], ab[na][0][3],
                                sa + a_off + AOFF[st + 1]);
                    ldmatrix_x4(ab[na][1][0], ab[na][1][1], ab[na][1][2], ab[na][1][3],
                                sa + a_off + 16 * ROWB + AOFF[st + 1]);
                    ldmatrix_x4(bb[0][0][0], bb[0][0][1], bb[0][1][0], bb[0][1][1],
                                sb + b_off + BOFF[st + 1]);
                }
                const int vb = bt & 1;
                mma_16816(acc[0][2 * bt],     ab[cb][0], bb[vb][0]);
                mma_16816(acc[0][2 * bt + 1], ab[cb][0], bb[vb][1]);
                mma_16816(acc[1][2 * bt],     ab[cb][1], bb[vb][0]);
                mma_16816(acc[1][2 * bt + 1], ab[cb][1], bb[vb][1]);
            }
        }

        sc = (sc + 1 == STAGES) ? 0 : sc + 1;
        sl = (sl + 1 == STAGES) ? 0 : sl + 1;
    }

    // ---- store S ----
#pragma unroll
    for (int mt = 0; mt < 2; mt++) {
        const int row = m0 + wm * 32 + mt * 16 + (lid >> 2);
#pragma unroll
        for (int nt = 0; nt < 8; nt++) {
            const int col = n0 + wn * 64 + nt * 8 + ((lid & 3) << 1);
            *(float2*)(C + (long long)row * N + col) =
                make_float2(acc[mt][nt][0], acc[mt][nt][1]);
            *(float2*)(C + (long long)(row + 8) * N + col) =
                make_float2(acc[mt][nt][2], acc[mt][nt][3]);
        }
    }

    // ---- softmax tile stats (rowmax, sum exp) ----
    CP_WAIT(0);
    __syncthreads();
    float* smax = (float*)smem;            // [2][128]
    float* ssum = (float*)(smem + 1024);   // [2][128]

    float mrow[2][2];
#pragma unroll
    for (int mt = 0; mt < 2; mt++)
#pragma unroll
        for (int h = 0; h < 2; h++) {
            float m = -3.0e38f;
#pragma unroll
            for (int nt = 0; nt < 8; nt++)
                m = fmaxf(m, fmaxf(acc[mt][nt][2 * h], acc[mt][nt][2 * h + 1]));
            m = fmaxf(m, __shfl_xor_sync(0xffffffffu, m, 1));
            m = fmaxf(m, __shfl_xor_sync(0xffffffffu, m, 2));
            const int rloc = wm * 32 + mt * 16 + h * 8 + (lid >> 2);
            if ((lid & 3) == 0) smax[wn * 128 + rloc] = m;
        }
    __syncthreads();
#pragma unroll
    for (int mt = 0; mt < 2; mt++)
#pragma unroll
        for (int h = 0; h < 2; h++) {
            const int rloc = wm * 32 + mt * 16 + h * 8 + (lid >> 2);
            mrow[mt][h] = fmaxf(smax[rloc], smax[128 + rloc]);
            float s = 0.0f;
#pragma unroll
            for (int nt = 0; nt < 8; nt++)
                s += __expf(acc[mt][nt][2 * h] - mrow[mt][h]) +
                     __expf(acc[mt][nt][2 * h + 1] - mrow[mt][h]);
            s += __shfl_xor_sync(0xffffffffu, s, 1);
            s += __shfl_xor_sync(0xffffffffu, s, 2);
            if ((lid & 3) == 0) ssum[wn * 128 + rloc] = s;
        }
    __syncthreads();
    if (wn == 0 && (lid & 3) == 0) {
#pragma unroll
        for (int mt = 0; mt < 2; mt++)
#pragma unroll
            for (int h = 0; h < 2; h++) {
                const int rloc = wm * 32 + mt * 16 + h * 8 + (lid >> 2);
                const long long row = (long long)blockIdx.z * TQ + m0 + rloc;
                stat[row * 16 + blockIdx.x] =
                    make_float2(mrow[mt][h], ssum[rloc] + ssum[128 + rloc]);
            }
    }
}

// ---------------------------------------------------------------------------
// Reduce 16 tile stats per row -> (rowmax, 1/rowsum)
// ---------------------------------------------------------------------------
__global__ void __launch_bounds__(256)
rowstat_kernel(const float2* __restrict__ stat, float2* __restrict__ rowinfo)
{
    const int idx = blockIdx.x * 256 + threadIdx.x;
    const float2* t = stat + (long long)idx * 16;
    float m = t[0].x;
#pragma unroll
    for (int i = 1; i < 16; i++) m = fmaxf(m, t[i].x);
    float s = 0.0f;
#pragma unroll
    for (int i = 0; i < 16; i++) s += t[i].y * __expf(t[i].x - m);
    rowinfo[idx] = make_float2(m, 1.0f / s);
}

// ===========================================================================
// GEMM2 (fused softmax): O = softmax(S) @ E.
// CTA 64m x 128n, k-chunk 64, chunk-major 3 sub-passes, 2-stage pipeline.
// NEW: 8 warps all along N (warp tile 64m x 16n): 5 LDSM per 8 MMAs.
// ===========================================================================
#define ROWB2  272                          // 128 bf16 (hi|lo) + 16B pad
#define A2_ST  (64 * ROWB2)                 // 17408
#define B2_ST  (128 * ROWB2)                // 34816
#define STG2   (A2_ST + B2_ST)              // 52224
#define GEMM2_SMEM (2 * STG2)               // 104448

__global__ void __launch_bounds__(256, 2)
gemm2_fused(const float* __restrict__ S, const __nv_bfloat16* __restrict__ Bm,
            const float2* __restrict__ rowinfo, float* __restrict__ O)
{
    extern __shared__ char smem[];
    const u32 smem_base = smem_u32(smem);

    constexpr int NC = TK / 64;   // 32 chunks

    const int tid = threadIdx.x;
    const int wid = tid >> 5;     // warp = n-slice (0..7)
    const int lid = tid & 31;

    const int bz = blockIdx.z;
    const int m0 = blockIdx.y * 64;
    const int n0 = blockIdx.x * 128;

    // A loader: 4 threads per row, 16 fp32 each
    const int ar = tid >> 2;
    const int aq = tid & 3;
    const float* Ap = S + ((long long)bz * TQ + m0 + ar) * TK + aq * 16;
    const float2 ri = rowinfo[(long long)bz * TQ + m0 + ar];
    const float m_r = ri.x, inv_r = ri.y;

    // B loader
    const int bs  = tid & 15;
    const int br0 = tid >> 4;
    const int bko = ((bs >> 3) & 1) * TK + (bs & 7) * 8;
    const __nv_bfloat16* Bp = Bm + ((long long)bz * DIM + n0) * (2 * TK) + bko;

    // fragment addresses (within stage)
    const int a_base = (lid & 15) * ROWB2 + ((lid >> 4) << 4);
    const int b_base = (wid * 16 + ((lid >> 4) << 3) + (lid & 7)) * ROWB2 +
                       (((lid >> 3) & 1) << 4);

    float acc[4][2][4];
#pragma unroll
    for (int mt = 0; mt < 4; mt++)
#pragma unroll
        for (int p = 0; p < 2; p++)
#pragma unroll
            for (int j = 0; j < 4; j++) acc[mt][p][j] = 0.0f;

    float4 av[4];

    auto lda = [&](int c) {
#pragma unroll
        for (int i = 0; i < 4; i++) av[i] = *(const float4*)(Ap + c * 64 + i * 4);
    };
    auto ldb = [&](int st, int c) {
        const u32 sb = smem_base + st * STG2 + A2_ST;
#pragma unroll
        for (int i = 0; i < 8; i++)
            CP_ASYNC_16(sb + (br0 + 16 * i) * ROWB2 + bs * 16,
                        Bp + (long long)(br0 + 16 * i) * (2 * TK) + c * 64);
    };
    auto cvta = [&](int st) {
        char* dst = smem + st * STG2 + ar * ROWB2 + aq * 32;
        u32 hi[8], lo[8];
        const float* f = (const float*)av;
#pragma unroll
        for (int j = 0; j < 8; j++) {
            const float p0 = __expf(f[2 * j]     - m_r) * inv_r;
            const float p1 = __expf(f[2 * j + 1] - m_r) * inv_r;
            const __nv_bfloat16 h0 = __float2bfloat16(p0);
            const __nv_bfloat16 h1 = __float2bfloat16(p1);
            const __nv_bfloat16 l0 = __float2bfloat16(p0 - __bfloat162float(h0));
            const __nv_bfloat16 l1 = __float2bfloat16(p1 - __bfloat162float(h1));
            __nv_bfloat162 hh, ll;
            hh.x = h0; hh.y = h1; ll.x = l0; ll.y = l1;
            hi[j] = *(u32*)&hh; lo[j] = *(u32*)&ll;
        }
        *(uint4*)(dst)            = make_uint4(hi[0], hi[1], hi[2], hi[3]);
        *(uint4*)(dst + 16)       = make_uint4(hi[4], hi[5], hi[6], hi[7]);
        *(uint4*)(dst + 128)      = make_uint4(lo[0], lo[1], lo[2], lo[3]);
        *(uint4*)(dst + 128 + 16) = make_uint4(lo[4], lo[5], lo[6], lo[7]);
    };

    lda(0);
    ldb(0, 0); CP_COMMIT();
    cvta(0);

    for (int c = 0; c < NC; c++) {
        CP_WAIT(0);
        __syncthreads();

        if (c + 1 < NC) {
            lda(c + 1);
            ldb((c + 1) & 1, c + 1);
            CP_COMMIT();
        }

        const u32 sa = smem_base + (c & 1) * STG2;
        const u32 sb = sa + A2_ST;

        u32 af[2][4][4], bf[2][4];
        // preload step 0 (sub0, ks0)
#pragma unroll
        for (int mt = 0; mt < 4; mt++)
            ldmatrix_x4(af[0][mt][0], af[0][mt][1], af[0][mt][2], af[0][mt][3],
                        sa + a_base + mt * 16 * ROWB2);
        ldmatrix_x4(bf[0][0], bf[0][1], bf[0][2], bf[0][3], sb + b_base);

#pragma unroll
        for (int s = 0; s < 12; s++) {
            const int cb = s & 1;
            if (s < 11) {
                const int s1   = s + 1;
                const int sub  = s1 >> 2;
                const int ks   = s1 & 3;
                const int aoff = ((sub == 1) ? 128 : 0) + ks * 32;
                const int boff = ((sub == 2) ? 128 : 0) + ks * 32;
                const int nb = s1 & 1;
#pragma unroll
                for (int mt = 0; mt < 4; mt++)
                    ldmatrix_x4(af[nb][mt][0], af[nb][mt][1], af[nb][mt][2], af[nb][mt][3],
                                sa + a_base + aoff + mt * 16 * ROWB2);
                ldmatrix_x4(bf[nb][0], bf[nb][1], bf[nb][2], bf[nb][3],
                            sb + b_base + boff);
            }
#pragma unroll
            for (int mt = 0; mt < 4; mt++) {
                mma_16816(acc[mt][0], af[cb][mt], &bf[cb][0]);
                mma_16816(acc[mt][1], af[cb][mt], &bf[cb][2]);
            }
        }

        if (c + 1 < NC) cvta((c + 1) & 1);
    }

    // ---- epilogue: O f32 ----
    O += (long long)bz * TQ * DIM;
#pragma unroll
    for (int mt = 0; mt < 4; mt++) {
        const int row = m0 + mt * 16 + (lid >> 2);
#pragma unroll
        for (int p = 0; p < 2; p++) {
            const int col = n0 + wid * 16 + p * 8 + ((lid & 3) << 1);
            *(float2*)(O + (long long)row * DIM + col) =
                make_float2(acc[mt][p][0], acc[mt][p][1]);
            *(float2*)(O + (long long)(row + 8) * DIM + col) =
                make_float2(acc[mt][p][2], acc[mt][p][3]);
        }
    }
}

// ---------------------------------------------------------------------------
// Fused E split: read E once, emit E2 (k-major hi|lo) and ET2 (transposed)
// ---------------------------------------------------------------------------
__global__ void __launch_bounds__(256)
esplit_kernel(const float* __restrict__ E, __nv_bfloat16* __restrict__ E2,
              __nv_bfloat16* __restrict__ ET2)
{
    __shared__ float sm[32][33];
    const int b  = blockIdx.z;
    const int t0 = blockIdx.x * 32;
    const int d0 = blockIdx.y * 32;
    const float* Eb = E + (long long)b * TK * DIM;
    __nv_bfloat16* E2b  = E2  + (long long)b * TK  * (2 * DIM);
    __nv_bfloat16* ET2b = ET2 + (long long)b * DIM * (2 * TK);
    const int tx = threadIdx.x, ty = threadIdx.y;

#pragma unroll
    for (int i = 0; i < 32; i += 8) {
        const float x = Eb[(long long)(t0 + ty + i) * DIM + d0 + tx];
        sm[ty + i][tx] = x;
        const __nv_bfloat16 hi = __float2bfloat16(x);
        const __nv_bfloat16 lo = __float2bfloat16(x - __bfloat162float(hi));
        __nv_bfloat16* row = E2b + (long long)(t0 + ty + i) * (2 * DIM);
        row[d0 + tx]       = hi;
        row[DIM + d0 + tx] = lo;
    }
    __syncthreads();

#pragma unroll
    for (int i = 0; i < 32; i += 8) {
        const int d = d0 + ty + i;
        const int t = t0 + tx;
        const float x = sm[tx][ty + i];
        const __nv_bfloat16 hi = __float2bfloat16(x);
        const __nv_bfloat16 lo = __float2bfloat16(x - __bfloat162float(hi));
        __nv_bfloat16* row = ET2b + (long long)d * (2 * TK);
        row[t]      = hi;
        row[TK + t] = lo;
    }
}

// ---------------------------------------------------------------------------
// Q split
// ---------------------------------------------------------------------------
template <int K>
__global__ void __launch_bounds__(256)
split2_kernel(const float* __restrict__ in, __nv_bfloat16* __restrict__ out,
              long long total)
{
    const long long n4 = total >> 2;
    for (long long i = (long long)blockIdx.x * blockDim.x + threadIdx.x;
         i < n4; i += (long long)gridDim.x * blockDim.x) {
        const long long e = i << 2;
        const long long r = e / K;
        const int k = (int)(e - r * (long long)K);
        const float4 x = *(const float4*)(in + e);
        const float xs[4] = {x.x, x.y, x.z, x.w};
        __nv_bfloat16 h[4], l[4];
#pragma unroll
        for (int j = 0; j < 4; j++) {
            h[j] = __float2bfloat16(xs[j]);
            l[j] = __float2bfloat16(xs[j] - __bfloat162float(h[j]));
        }
        __nv_bfloat16* o = out + r * (2LL * K) + k;
        __nv_bfloat162 hh0, hh1, ll0, ll1;
        hh0.x = h[0]; hh0.y = h[1]; hh1.x = h[2]; hh1.y = h[3];
        ll0.x = l[0]; ll0.y = l[1]; ll1.x = l[2]; ll1.y = l[3];
        *(__nv_bfloat162*)(o + 0)     = hh0;
        *(__nv_bfloat162*)(o + 2)     = hh1;
        *(__nv_bfloat162*)(o + K)     = ll0;
        *(__nv_bfloat162*)(o + K + 2) = ll1;
    }
}

// ---------------------------------------------------------------------------
// Entry point
// ---------------------------------------------------------------------------
extern "C" void kernel_launch(void* const* d_in, const int* in_sizes, int n_in,
                              void* d_out, int out_size)
{
    const float* Q = (const float*)d_in[0];
    const float* E = (const float*)d_in[1];
    float* O = (float*)d_out;

    __nv_bfloat16 *Q2, *E2, *ET2;
    float* S;
    float2 *stat, *rowi;
    cudaGetSymbolAddress((void**)&Q2,   g_Q2);
    cudaGetSymbolAddress((void**)&E2,   g_E2);
    cudaGetSymbolAddress((void**)&S,    g_S);
    cudaGetSymbolAddress((void**)&ET2,  g_ET2);
    cudaGetSymbolAddress((void**)&stat, g_stat);
    cudaGetSymbolAddress((void**)&rowi, g_row);

    cudaFuncSetAttribute(gemm1_stats, cudaFuncAttributeMaxDynamicSharedMemorySize, GEMM_SMEM);
    cudaFuncSetAttribute(gemm2_fused, cudaFuncAttributeMaxDynamicSharedMemorySize, GEMM2_SMEM);

    split2_kernel<DIM><<<8192, 256>>>(Q, Q2, (long long)BATCH * TQ * DIM);
    esplit_kernel<<<dim3(TK / 32, DIM / 32, BATCH), dim3(32, 8)>>>(E, E2, ET2);

    gemm1_stats<<<dim3(TK / 128, TQ / 128, BATCH), 256, GEMM_SMEM>>>(Q2, E2, S, stat);

    rowstat_kernel<<<BATCH * TQ / 256, 256>>>(stat, rowi);

    gemm2_fused<<<dim3(DIM / 128, TQ / 64, BATCH), 256, GEMM2_SMEM>>>(S, ET2, rowi, O);
}

// round 14
// speedup vs baseline: 1.1443x; 1.1443x over previous
#include <cuda_runtime.h>
#include <cuda_bf16.h>

typedef unsigned int       u32;
typedef unsigned long long u64;

#define BATCH 32
#define TQ    512
#define TK    2048
#define DIM   512

// ---------------------------------------------------------------------------
// Scratch. 2-section split storage: row = [hi(K) | lo(K)].
// Product = hi*hi + lo*hi + hi*lo (fp32 minus O(2^-18) lo*lo term)
// ---------------------------------------------------------------------------
__device__ __nv_bfloat16 g_Q2 [(size_t)BATCH * TQ  * 2 * DIM];  //  34 MB
__device__ __nv_bfloat16 g_E2 [(size_t)BATCH * TK  * 2 * DIM];  // 134 MB
__device__ float         g_S  [(size_t)BATCH * TQ  * TK];       // 134 MB
__device__ float2        g_stat[(size_t)BATCH * TQ * (TK / 128)]; // 2 MB
__device__ float2        g_row [(size_t)BATCH * TQ];              // 128 KB

// ---------------------------------------------------------------------------
// Baseline-PTX tensor-core helpers
// ---------------------------------------------------------------------------
__device__ __forceinline__ u32 smem_u32(const void* p) {
    u32 a;
    asm("{ .reg .u64 t; cvta.to.shared.u64 t, %1; cvt.u32.u64 %0, t; }"
        : "=r"(a) : "l"(p));
    return a;
}

__device__ __forceinline__ void ldmatrix_x4(u32& r0, u32& r1, u32& r2, u32& r3,
                                            u32 addr) {
    asm volatile("ldmatrix.sync.aligned.m8n8.x4.shared.b16 {%0,%1,%2,%3}, [%4];"
                 : "=r"(r0), "=r"(r1), "=r"(r2), "=r"(r3) : "r"(addr));
}

__device__ __forceinline__ void ldmatrix_x4_trans(u32& r0, u32& r1, u32& r2, u32& r3,
                                                  u32 addr) {
    asm volatile("ldmatrix.sync.aligned.m8n8.x4.trans.shared.b16 {%0,%1,%2,%3}, [%4];"
                 : "=r"(r0), "=r"(r1), "=r"(r2), "=r"(r3) : "r"(addr));
}

__device__ __forceinline__ void mma_16816(float* c, const u32* a, const u32* b) {
    asm volatile(
        "mma.sync.aligned.m16n8k16.row.col.f32.bf16.bf16.f32 "
        "{%0,%1,%2,%3}, {%4,%5,%6,%7}, {%8,%9}, {%0,%1,%2,%3};"
        : "+f"(c[0]), "+f"(c[1]), "+f"(c[2]), "+f"(c[3])
        : "r"(a[0]), "r"(a[1]), "r"(a[2]), "r"(a[3]), "r"(b[0]), "r"(b[1]));
}

#define CP_ASYNC_16(saddr, gptr) \
    asm volatile("cp.async.cg.shared.global [%0], [%1], 16;" \
                 :: "r"(saddr), "l"(gptr) : "memory")
#define CP_COMMIT() asm volatile("cp.async.commit_group;" ::: "memory")
#define CP_WAIT(n)  asm volatile("cp.async.wait_group %0;" :: "n"(n) : "memory")

// ===========================================================================
// GEMM1: S = Q @ E^T (3-pass split, K=512/section) + per-tile softmax stats.
// CTA 128x128, BK=64, 3-stage cp.async, 8 warps (32m x 64n warp tiles).
// (R12 kernel, verbatim — proven 307us mainloop.)
// ===========================================================================
#define STAGES     3
#define ROWB       144
#define TILE_BYTES (128 * ROWB)
#define STAGE_BYTES (2 * TILE_BYTES)
#define GEMM_SMEM  (STAGES * STAGE_BYTES)    // 110592

__global__ void __launch_bounds__(256, 2)
gemm1_stats(const __nv_bfloat16* __restrict__ A, const __nv_bfloat16* __restrict__ B,
            float* __restrict__ C, float2* __restrict__ stat)
{
    extern __shared__ char smem[];
    const u32 smem_base = smem_u32(smem);

    constexpr int K   = DIM;
    constexpr int KT  = 2 * K;
    constexpr int NCH = K / 64;
    constexpr int NC  = 3 * NCH;
    constexpr int N   = TK;

    const int tid = threadIdx.x;
    const int wid = tid >> 5;
    const int lid = tid & 31;
    const int wm  = wid & 3;
    const int wn  = wid >> 2;

    A += (long long)blockIdx.z * (TQ * (long long)KT);
    B += (long long)blockIdx.z * (TK * (long long)KT);
    C += (long long)blockIdx.z * ((long long)TQ * TK);
    const int m0 = blockIdx.y * 128;
    const int n0 = blockIdx.x * 128;

    const int q  = tid & 7;
    const int r0 = tid >> 3;

    const int a_off = (wm * 32 + (lid & 15)) * ROWB + ((lid >> 4) << 4);
    const int b_off = (wn * 64 + ((lid >> 4) << 3) + (lid & 7)) * ROWB +
                      (((lid >> 3) & 1) << 4);

    float acc[2][8][4];
#pragma unroll
    for (int mt = 0; mt < 2; mt++)
#pragma unroll
        for (int nt = 0; nt < 8; nt++)
#pragma unroll
            for (int j = 0; j < 4; j++) acc[mt][nt][j] = 0.0f;

    auto load_stage = [&](int s, int c) {
        const int pass = c / NCH;
        const int kk   = c - pass * NCH;
        const int ka   = ((pass == 1) ? K : 0) + kk * 64;
        const int kb   = ((pass == 2) ? K : 0) + kk * 64;
        const u32 sa = smem_base + s * STAGE_BYTES;
        const u32 sb = sa + TILE_BYTES;
        const __nv_bfloat16* Ap = A + (long long)(m0 + r0) * KT + ka + q * 8;
        const __nv_bfloat16* Bp = B + (long long)(n0 + r0) * KT + kb + q * 8;
#pragma unroll
        for (int i = 0; i < 4; i++) {
            CP_ASYNC_16(sa + (r0 + i * 32) * ROWB + q * 16, Ap + (long long)(i * 32) * KT);
            CP_ASYNC_16(sb + (r0 + i * 32) * ROWB + q * 16, Bp + (long long)(i * 32) * KT);
        }
    };

    load_stage(0, 0); CP_COMMIT();
    load_stage(1, 1); CP_COMMIT();

    int sc = 0, sl = 2;
    for (int c = 0; c < NC; c++) {
        CP_WAIT(1);
        __syncthreads();

        if (c + 2 < NC) load_stage(sl, c + 2);
        CP_COMMIT();

        const u32 sa = smem_base + sc * STAGE_BYTES;
        const u32 sb = sa + TILE_BYTES;

        u32 ab[2][2][4];
        u32 bb[2][2][2];

        ldmatrix_x4(ab[0][0][0], ab[0][0][1], ab[0][0][2], ab[0][0][3], sa + a_off);
        ldmatrix_x4(ab[0][1][0], ab[0][1][1], ab[0][1][2], ab[0][1][3],
                    sa + a_off + 16 * ROWB);
        ldmatrix_x4(bb[0][0][0], bb[0][0][1], bb[0][1][0], bb[0][1][1], sb + b_off);

#pragma unroll
        for (int ks = 0; ks < 4; ks++) {
            const int cb = ks & 1;
#pragma unroll
            for (int bt = 0; bt < 4; bt++) {
                if (bt < 3) {
                    const int nb = (bt + 1) & 1;
                    ldmatrix_x4(bb[nb][0][0], bb[nb][0][1], bb[nb][1][0], bb[nb][1][1],
                                sb + b_off + (bt + 1) * 16 * ROWB + ks * 32);
                } else if (ks < 3) {
                    const int na = (ks + 1) & 1;
                    ldmatrix_x4(ab[na][0][0], ab[na][0][1], ab[na][0][2], ab[na][0][3],
                                sa + a_off + (ks + 1) * 32);
                    ldmatrix_x4(ab[na][1][0], ab[na][1][1], ab[na][1][2], ab[na][1][3],
                                sa + a_off + 16 * ROWB + (ks + 1) * 32);
                    ldmatrix_x4(bb[0][0][0], bb[0][0][1], bb[0][1][0], bb[0][1][1],
                                sb + b_off + (ks + 1) * 32);
                }
                const int vb = bt & 1;
                mma_16816(acc[0][2 * bt],     ab[cb][0], bb[vb][0]);
                mma_16816(acc[0][2 * bt + 1], ab[cb][0], bb[vb][1]);
                mma_16816(acc[1][2 * bt],     ab[cb][1], bb[vb][0]);
                mma_16816(acc[1][2 * bt + 1], ab[cb][1], bb[vb][1]);
            }
        }

        sc = (sc + 1 == STAGES) ? 0 : sc + 1;
        sl = (sl + 1 == STAGES) ? 0 : sl + 1;
    }

    // ---- store S ----
#pragma unroll
    for (int mt = 0; mt < 2; mt++) {
        const int row = m0 + wm * 32 + mt * 16 + (lid >> 2);
#pragma unroll
        for (int nt = 0; nt < 8; nt++) {
            const int col = n0 + wn * 64 + nt * 8 + ((lid & 3) << 1);
            *(float2*)(C + (long long)row * N + col) =
                make_float2(acc[mt][nt][0], acc[mt][nt][1]);
            *(float2*)(C + (long long)(row + 8) * N + col) =
                make_float2(acc[mt][nt][2], acc[mt][nt][3]);
        }
    }

    // ---- softmax tile stats ----
    CP_WAIT(0);
    __syncthreads();
    float* smax = (float*)smem;
    float* ssum = (float*)(smem + 1024);

    float mrow[2][2];
#pragma unroll
    for (int mt = 0; mt < 2; mt++)
#pragma unroll
        for (int h = 0; h < 2; h++) {
            float m = -3.0e38f;
#pragma unroll
            for (int nt = 0; nt < 8; nt++)
                m = fmaxf(m, fmaxf(acc[mt][nt][2 * h], acc[mt][nt][2 * h + 1]));
            m = fmaxf(m, __shfl_xor_sync(0xffffffffu, m, 1));
            m = fmaxf(m, __shfl_xor_sync(0xffffffffu, m, 2));
            const int rloc = wm * 32 + mt * 16 + h * 8 + (lid >> 2);
            if ((lid & 3) == 0) smax[wn * 128 + rloc] = m;
        }
    __syncthreads();
#pragma unroll
    for (int mt = 0; mt < 2; mt++)
#pragma unroll
        for (int h = 0; h < 2; h++) {
            const int rloc = wm * 32 + mt * 16 + h * 8 + (lid >> 2);
            mrow[mt][h] = fmaxf(smax[rloc], smax[128 + rloc]);
            float s = 0.0f;
#pragma unroll
            for (int nt = 0; nt < 8; nt++)
                s += __expf(acc[mt][nt][2 * h] - mrow[mt][h]) +
                     __expf(acc[mt][nt][2 * h + 1] - mrow[mt][h]);
            s += __shfl_xor_sync(0xffffffffu, s, 1);
            s += __shfl_xor_sync(0xffffffffu, s, 2);
            if ((lid & 3) == 0) ssum[wn * 128 + rloc] = s;
        }
    __syncthreads();
    if (wn == 0 && (lid & 3) == 0) {
#pragma unroll
        for (int mt = 0; mt < 2; mt++)
#pragma unroll
            for (int h = 0; h < 2; h++) {
                const int rloc = wm * 32 + mt * 16 + h * 8 + (lid >> 2);
                const long long row = (long long)blockIdx.z * TQ + m0 + rloc;
                stat[row * 16 + blockIdx.x] =
                    make_float2(mrow[mt][h], ssum[rloc] + ssum[128 + rloc]);
            }
    }
}

// ---------------------------------------------------------------------------
// Reduce 16 tile stats per row -> (rowmax, 1/rowsum)
// ---------------------------------------------------------------------------
__global__ void __launch_bounds__(256)
rowstat_kernel(const float2* __restrict__ stat, float2* __restrict__ rowinfo)
{
    const int idx = blockIdx.x * 256 + threadIdx.x;
    const float2* t = stat + (long long)idx * 16;
    float m = t[0].x;
#pragma unroll
    for (int i = 1; i < 16; i++) m = fmaxf(m, t[i].x);
    float s = 0.0f;
#pragma unroll
    for (int i = 0; i < 16; i++) s += t[i].y * __expf(t[i].x - m);
    rowinfo[idx] = make_float2(m, 1.0f / s);
}

// ===========================================================================
// GEMM2 (fused softmax): O = softmax(S) @ E.
// R12 tiling (CTA 64m x 128n, warps 2m x 4n = 32x32 tiles, 2-stage pipeline).
// B is read DIRECTLY from k-major E2 via ldmatrix.x4.trans (no ET2 buffer):
//   smem B tile = 64 token rows x [hi 256B | lo 256B], row stride 560B
//   (stride mod 128 cycles 0,48,96,16,64,112,32,80 -> conflict-free LDSM).
// ===========================================================================
#define ROWB2A 272                          // A row stride
#define ROWB2B 560                          // B row stride (512 data + 48 pad)
#define A2_ST  (64 * ROWB2A)                // 17408
#define B2_ST  (64 * ROWB2B)                // 35840
#define STG2   (A2_ST + B2_ST)              // 53248
#define GEMM2_SMEM (2 * STG2)               // 106496

__global__ void __launch_bounds__(256, 2)
gemm2_fused(const float* __restrict__ S, const __nv_bfloat16* __restrict__ E2,
            const float2* __restrict__ rowinfo, float* __restrict__ O)
{
    extern __shared__ char smem[];
    const u32 smem_base = smem_u32(smem);

    constexpr int NC = TK / 64;   // 32 chunks

    const int tid = threadIdx.x;
    const int wid = tid >> 5;
    const int lid = tid & 31;
    const int wm  = wid & 1;      // 2 warps along M (32 rows)
    const int wn  = wid >> 1;     // 4 warps along N (32 cols)

    const int bz = blockIdx.z;
    const int m0 = blockIdx.y * 64;
    const int n0 = blockIdx.x * 128;

    // A loader: 4 threads per row, 16 fp32 each
    const int ar = tid >> 2;
    const int aq = tid & 3;
    const float* Ap = S + ((long long)bz * TQ + m0 + ar) * TK + aq * 16;
    const float2 ri = rowinfo[(long long)bz * TQ + m0 + ar];
    const float m_r = ri.x, inv_r = ri.y;

    // B loader: 4 threads per token row, 8 x 16B chunks each (32 per row)
    const int br = tid >> 2;            // 0..63 token row within chunk
    const int bq = tid & 3;
    const __nv_bfloat16* Bp = E2 + ((long long)bz * TK + br) * (2 * DIM);

    // fragment addresses (within stage)
    const int a_base = (wm * 32 + (lid & 15)) * ROWB2A + ((lid >> 4) << 4);
    // trans-B: lanes 0-15 -> k rows 0-15, lanes 16-31 same rows at +16B (n+8)
    const int b_base = (lid & 15) * ROWB2B + ((lid >> 4) << 4) + wn * 64;

    float acc[2][4][4];
#pragma unroll
    for (int mt = 0; mt < 2; mt++)
#pragma unroll
        for (int nt = 0; nt < 4; nt++)
#pragma unroll
            for (int j = 0; j < 4; j++) acc[mt][nt][j] = 0.0f;

    float4 av[4];

    auto lda = [&](int c) {
#pragma unroll
        for (int i = 0; i < 4; i++) av[i] = *(const float4*)(Ap + c * 64 + i * 4);
    };
    auto ldb = [&](int st, int c) {
        const u32 sb = smem_base + st * STG2 + A2_ST;
        const __nv_bfloat16* src = Bp + (long long)c * 64 * (2 * DIM);
#pragma unroll
        for (int i = 0; i < 8; i++) {
            const int cc = bq + 4 * i;                       // 0..31
            const int go = (cc < 16) ? (n0 + cc * 8) : (DIM + n0 + (cc - 16) * 8);
            CP_ASYNC_16(sb + br * ROWB2B + cc * 16, src + go);
        }
    };
    auto cvta = [&](int st) {
        char* dst = smem + st * STG2 + ar * ROWB2A + aq * 32;
        u32 hi[8], lo[8];
        const float* f = (const float*)av;
#pragma unroll
        for (int j = 0; j < 8; j++) {
            const float p0 = __expf(f[2 * j]     - m_r) * inv_r;
            const float p1 = __expf(f[2 * j + 1] - m_r) * inv_r;
            const __nv_bfloat16 h0 = __float2bfloat16(p0);
            const __nv_bfloat16 h1 = __float2bfloat16(p1);
            const __nv_bfloat16 l0 = __float2bfloat16(p0 - __bfloat162float(h0));
            const __nv_bfloat16 l1 = __float2bfloat16(p1 - __bfloat162float(h1));
            __nv_bfloat162 hh, ll;
            hh.x = h0; hh.y = h1; ll.x = l0; ll.y = l1;
            hi[j] = *(u32*)&hh; lo[j] = *(u32*)&ll;
        }
        *(uint4*)(dst)            = make_uint4(hi[0], hi[1], hi[2], hi[3]);
        *(uint4*)(dst + 16)       = make_uint4(hi[4], hi[5], hi[6], hi[7]);
        *(uint4*)(dst + 128)      = make_uint4(lo[0], lo[1], lo[2], lo[3]);
        *(uint4*)(dst + 128 + 16) = make_uint4(lo[4], lo[5], lo[6], lo[7]);
    };

    lda(0);
    ldb(0, 0); CP_COMMIT();
    cvta(0);

    for (int c = 0; c < NC; c++) {
        CP_WAIT(0);
        __syncthreads();

        if (c + 1 < NC) {
            lda(c + 1);
            ldb((c + 1) & 1, c + 1);
            CP_COMMIT();
        }

        const u32 sa = smem_base + (c & 1) * STG2;
        const u32 sb = sa + A2_ST;

        u32 af[2][2][4], bf[2][2][4];
        // preload step 0 (sub0, ks0): A hi, B hi
        ldmatrix_x4(af[0][0][0], af[0][0][1], af[0][0][2], af[0][0][3], sa + a_base);
        ldmatrix_x4(af[0][1][0], af[0][1][1], af[0][1][2], af[0][1][3],
                    sa + a_base + 16 * ROWB2A);
        ldmatrix_x4_trans(bf[0][0][0], bf[0][0][1], bf[0][0][2], bf[0][0][3],
                          sb + b_base);
        ldmatrix_x4_trans(bf[0][1][0], bf[0][1][1], bf[0][1][2], bf[0][1][3],
                          sb + b_base + 32);

#pragma unroll
        for (int s = 0; s < 12; s++) {
            const int cb = s & 1;
            if (s < 11) {
                const int s1   = s + 1;
                const int sub  = s1 >> 2;
                const int ks   = s1 & 3;
                const int aoff = ((sub == 1) ? 128 : 0) + ks * 32;
                // B: rows advance by k (16 per kstep), lo section at +256B
                const int boff = ks * 16 * ROWB2B + ((sub == 2) ? 256 : 0);
                const int nb = s1 & 1;
                ldmatrix_x4(af[nb][0][0], af[nb][0][1], af[nb][0][2], af[nb][0][3],
                            sa + a_base + aoff);
                ldmatrix_x4(af[nb][1][0], af[nb][1][1], af[nb][1][2], af[nb][1][3],
                            sa + a_base + aoff + 16 * ROWB2A);
                ldmatrix_x4_trans(bf[nb][0][0], bf[nb][0][1], bf[nb][0][2], bf[nb][0][3],
                                  sb + b_base + boff);
                ldmatrix_x4_trans(bf[nb][1][0], bf[nb][1][1], bf[nb][1][2], bf[nb][1][3],
                                  sb + b_base + boff + 32);
            }
#pragma unroll
            for (int mt = 0; mt < 2; mt++)
#pragma unroll
                for (int h = 0; h < 2; h++) {
                    mma_16816(acc[mt][2 * h],     af[cb][mt], &bf[cb][h][0]);
                    mma_16816(acc[mt][2 * h + 1], af[cb][mt], &bf[cb][h][2]);
                }
        }

        if (c + 1 < NC) cvta((c + 1) & 1);
    }

    // ---- epilogue: O f32 ----
    O += (long long)bz * TQ * DIM;
#pragma unroll
    for (int mt = 0; mt < 2; mt++) {
        const int row = m0 + wm * 32 + mt * 16 + (lid >> 2);
#pragma unroll
        for (int nt = 0; nt < 4; nt++) {
            const int col = n0 + wn * 32 + nt * 8 + ((lid & 3) << 1);
            *(float2*)(O + (long long)row * DIM + col) =
                make_float2(acc[mt][nt][0], acc[mt][nt][1]);
            *(float2*)(O + (long long)(row + 8) * DIM + col) =
                make_float2(acc[mt][nt][2], acc[mt][nt][3]);
        }
    }
}

// ---------------------------------------------------------------------------
// Row-wise hi/lo split (used for both Q and E)
// ---------------------------------------------------------------------------
template <int K>
__global__ void __launch_bounds__(256)
split2_kernel(const float* __restrict__ in, __nv_bfloat16* __restrict__ out,
              long long total)
{
    const long long n4 = total >> 2;
    for (long long i = (long long)blockIdx.x * blockDim.x + threadIdx.x;
         i < n4; i += (long long)gridDim.x * blockDim.x) {
        const long long e = i << 2;
        const long long r = e / K;
        const int k = (int)(e - r * (long long)K);
        const float4 x = *(const float4*)(in + e);
        const float xs[4] = {x.x, x.y, x.z, x.w};
        __nv_bfloat16 h[4], l[4];
#pragma unroll
        for (int j = 0; j < 4; j++) {
            h[j] = __float2bfloat16(xs[j]);
            l[j] = __float2bfloat16(xs[j] - __bfloat162float(h[j]));
        }
        __nv_bfloat16* o = out + r * (2LL * K) + k;
        __nv_bfloat162 hh0, hh1, ll0, ll1;
        hh0.x = h[0]; hh0.y = h[1]; hh1.x = h[2]; hh1.y = h[3];
        ll0.x = l[0]; ll0.y = l[1]; ll1.x = l[2]; ll1.y = l[3];
        *(__nv_bfloat162*)(o + 0)     = hh0;
        *(__nv_bfloat162*)(o + 2)     = hh1;
        *(__nv_bfloat162*)(o + K)     = ll0;
        *(__nv_bfloat162*)(o + K + 2) = ll1;
    }
}

// ---------------------------------------------------------------------------
// Entry point
// ---------------------------------------------------------------------------
extern "C" void kernel_launch(void* const* d_in, const int* in_sizes, int n_in,
                              void* d_out, int out_size)
{
    const float* Q = (const float*)d_in[0];
    const float* E = (const float*)d_in[1];
    float* O = (float*)d_out;

    __nv_bfloat16 *Q2, *E2;
    float* S;
    float2 *stat, *rowi;
    cudaGetSymbolAddress((void**)&Q2,   g_Q2);
    cudaGetSymbolAddress((void**)&E2,   g_E2);
    cudaGetSymbolAddress((void**)&S,    g_S);
    cudaGetSymbolAddress((void**)&stat, g_stat);
    cudaGetSymbolAddress((void**)&rowi, g_row);

    cudaFuncSetAttribute(gemm1_stats, cudaFuncAttributeMaxDynamicSharedMemorySize, GEMM_SMEM);
    cudaFuncSetAttribute(gemm2_fused, cudaFuncAttributeMaxDynamicSharedMemorySize, GEMM2_SMEM);

    // operand conversions (no transpose needed anymore)
    split2_kernel<DIM><<<8192, 256>>>(Q, Q2, (long long)BATCH * TQ * DIM);
    split2_kernel<DIM><<<32768, 256>>>(E, E2, (long long)BATCH * TK * DIM);

    // S = Q @ E^T  + per-tile softmax stats
    gemm1_stats<<<dim3(TK / 128, TQ / 128, BATCH), 256, GEMM_SMEM>>>(Q2, E2, S, stat);

    // merge tile stats -> per-row (max, 1/sum)
    rowstat_kernel<<<BATCH * TQ / 256, 256>>>(stat, rowi);

    // O = softmax(S) @ E  (B via trans-ldmatrix straight from E2)
    gemm2_fused<<<dim3(DIM / 128, TQ / 64, BATCH), 256, GEMM2_SMEM>>>(S, E2, rowi, O);
}

// round 15
// speedup vs baseline: 1.1564x; 1.0106x over previous
#include <cuda_runtime.h>
#include <cuda_bf16.h>

typedef unsigned int       u32;
typedef unsigned long long u64;

#define BATCH 32
#define TQ    512
#define TK    2048
#define DIM   512

// ---------------------------------------------------------------------------
// Scratch. 2-section split storage: row = [hi(K) | lo(K)].
// Product = hi*hi + lo*hi + hi*lo (fp32 minus O(2^-18) lo*lo term)
// ---------------------------------------------------------------------------
__device__ __nv_bfloat16 g_Q2 [(size_t)BATCH * TQ  * 2 * DIM];  //  34 MB
__device__ __nv_bfloat16 g_E2 [(size_t)BATCH * TK  * 2 * DIM];  // 134 MB
__device__ float         g_S  [(size_t)BATCH * TQ  * TK];       // 134 MB
__device__ float2        g_stat[(size_t)BATCH * TQ * (TK / 128)]; // 2 MB
__device__ float2        g_row [(size_t)BATCH * TQ];              // 128 KB

// ---------------------------------------------------------------------------
// Baseline-PTX tensor-core helpers
// ---------------------------------------------------------------------------
__device__ __forceinline__ u32 smem_u32(const void* p) {
    u32 a;
    asm("{ .reg .u64 t; cvta.to.shared.u64 t, %1; cvt.u32.u64 %0, t; }"
        : "=r"(a) : "l"(p));
    return a;
}

__device__ __forceinline__ void ldmatrix_x4(u32& r0, u32& r1, u32& r2, u32& r3,
                                            u32 addr) {
    asm volatile("ldmatrix.sync.aligned.m8n8.x4.shared.b16 {%0,%1,%2,%3}, [%4];"
                 : "=r"(r0), "=r"(r1), "=r"(r2), "=r"(r3) : "r"(addr));
}

__device__ __forceinline__ void ldmatrix_x4_trans(u32& r0, u32& r1, u32& r2, u32& r3,
                                                  u32 addr) {
    asm volatile("ldmatrix.sync.aligned.m8n8.x4.trans.shared.b16 {%0,%1,%2,%3}, [%4];"
                 : "=r"(r0), "=r"(r1), "=r"(r2), "=r"(r3) : "r"(addr));
}

__device__ __forceinline__ void mma_16816(float* c, const u32* a, const u32* b) {
    asm volatile(
        "mma.sync.aligned.m16n8k16.row.col.f32.bf16.bf16.f32 "
        "{%0,%1,%2,%3}, {%4,%5,%6,%7}, {%8,%9}, {%0,%1,%2,%3};"
        : "+f"(c[0]), "+f"(c[1]), "+f"(c[2]), "+f"(c[3])
        : "r"(a[0]), "r"(a[1]), "r"(a[2]), "r"(a[3]), "r"(b[0]), "r"(b[1]));
}

#define CP_ASYNC_16(saddr, gptr) \
    asm volatile("cp.async.cg.shared.global [%0], [%1], 16;" \
                 :: "r"(saddr), "l"(gptr) : "memory")
#define CP_COMMIT() asm volatile("cp.async.commit_group;" ::: "memory")
#define CP_WAIT(n)  asm volatile("cp.async.wait_group %0;" :: "n"(n) : "memory")

// ===========================================================================
// GEMM1: S = Q @ E^T (3-pass split, K=512/section) + per-tile softmax stats.
// CTA 128x128, BK=64, 3-stage cp.async, 8 warps (32m x 64n warp tiles).
// (R12/R14 kernel, verbatim — proven mainloop.)
// ===========================================================================
#define STAGES     3
#define ROWB       144
#define TILE_BYTES (128 * ROWB)
#define STAGE_BYTES (2 * TILE_BYTES)
#define GEMM_SMEM  (STAGES * STAGE_BYTES)    // 110592

__global__ void __launch_bounds__(256, 2)
gemm1_stats(const __nv_bfloat16* __restrict__ A, const __nv_bfloat16* __restrict__ B,
            float* __restrict__ C, float2* __restrict__ stat)
{
    extern __shared__ char smem[];
    const u32 smem_base = smem_u32(smem);

    constexpr int K   = DIM;
    constexpr int KT  = 2 * K;
    constexpr int NCH = K / 64;
    constexpr int NC  = 3 * NCH;
    constexpr int N   = TK;

    const int tid = threadIdx.x;
    const int wid = tid >> 5;
    const int lid = tid & 31;
    const int wm  = wid & 3;
    const int wn  = wid >> 2;

    A += (long long)blockIdx.z * (TQ * (long long)KT);
    B += (long long)blockIdx.z * (TK * (long long)KT);
    C += (long long)blockIdx.z * ((long long)TQ * TK);
    const int m0 = blockIdx.y * 128;
    const int n0 = blockIdx.x * 128;

    const int q  = tid & 7;
    const int r0 = tid >> 3;

    const int a_off = (wm * 32 + (lid & 15)) * ROWB + ((lid >> 4) << 4);
    const int b_off = (wn * 64 + ((lid >> 4) << 3) + (lid & 7)) * ROWB +
                      (((lid >> 3) & 1) << 4);

    float acc[2][8][4];
#pragma unroll
    for (int mt = 0; mt < 2; mt++)
#pragma unroll
        for (int nt = 0; nt < 8; nt++)
#pragma unroll
            for (int j = 0; j < 4; j++) acc[mt][nt][j] = 0.0f;

    auto load_stage = [&](int s, int c) {
        const int pass = c / NCH;
        const int kk   = c - pass * NCH;
        const int ka   = ((pass == 1) ? K : 0) + kk * 64;
        const int kb   = ((pass == 2) ? K : 0) + kk * 64;
        const u32 sa = smem_base + s * STAGE_BYTES;
        const u32 sb = sa + TILE_BYTES;
        const __nv_bfloat16* Ap = A + (long long)(m0 + r0) * KT + ka + q * 8;
        const __nv_bfloat16* Bp = B + (long long)(n0 + r0) * KT + kb + q * 8;
#pragma unroll
        for (int i = 0; i < 4; i++) {
            CP_ASYNC_16(sa + (r0 + i * 32) * ROWB + q * 16, Ap + (long long)(i * 32) * KT);
            CP_ASYNC_16(sb + (r0 + i * 32) * ROWB + q * 16, Bp + (long long)(i * 32) * KT);
        }
    };

    load_stage(0, 0); CP_COMMIT();
    load_stage(1, 1); CP_COMMIT();

    int sc = 0, sl = 2;
    for (int c = 0; c < NC; c++) {
        CP_WAIT(1);
        __syncthreads();

        if (c + 2 < NC) load_stage(sl, c + 2);
        CP_COMMIT();

        const u32 sa = smem_base + sc * STAGE_BYTES;
        const u32 sb = sa + TILE_BYTES;

        u32 ab[2][2][4];
        u32 bb[2][2][2];

        ldmatrix_x4(ab[0][0][0], ab[0][0][1], ab[0][0][2], ab[0][0][3], sa + a_off);
        ldmatrix_x4(ab[0][1][0], ab[0][1][1], ab[0][1][2], ab[0][1][3],
                    sa + a_off + 16 * ROWB);
        ldmatrix_x4(bb[0][0][0], bb[0][0][1], bb[0][1][0], bb[0][1][1], sb + b_off);

#pragma unroll
        for (int ks = 0; ks < 4; ks++) {
            const int cb = ks & 1;
#pragma unroll
            for (int bt = 0; bt < 4; bt++) {
                if (bt < 3) {
                    const int nb = (bt + 1) & 1;
                    ldmatrix_x4(bb[nb][0][0], bb[nb][0][1], bb[nb][1][0], bb[nb][1][1],
                                sb + b_off + (bt + 1) * 16 * ROWB + ks * 32);
                } else if (ks < 3) {
                    const int na = (ks + 1) & 1;
                    ldmatrix_x4(ab[na][0][0], ab[na][0][1], ab[na][0][2], ab[na][0][3],
                                sa + a_off + (ks + 1) * 32);
                    ldmatrix_x4(ab[na][1][0], ab[na][1][1], ab[na][1][2], ab[na][1][3],
                                sa + a_off + 16 * ROWB + (ks + 1) * 32);
                    ldmatrix_x4(bb[0][0][0], bb[0][0][1], bb[0][1][0], bb[0][1][1],
                                sb + b_off + (ks + 1) * 32);
                }
                const int vb = bt & 1;
                mma_16816(acc[0][2 * bt],     ab[cb][0], bb[vb][0]);
                mma_16816(acc[0][2 * bt + 1], ab[cb][0], bb[vb][1]);
                mma_16816(acc[1][2 * bt],     ab[cb][1], bb[vb][0]);
                mma_16816(acc[1][2 * bt + 1], ab[cb][1], bb[vb][1]);
            }
        }

        sc = (sc + 1 == STAGES) ? 0 : sc + 1;
        sl = (sl + 1 == STAGES) ? 0 : sl + 1;
    }

    // ---- store S ----
#pragma unroll
    for (int mt = 0; mt < 2; mt++) {
        const int row = m0 + wm * 32 + mt * 16 + (lid >> 2);
#pragma unroll
        for (int nt = 0; nt < 8; nt++) {
            const int col = n0 + wn * 64 + nt * 8 + ((lid & 3) << 1);
            *(float2*)(C + (long long)row * N + col) =
                make_float2(acc[mt][nt][0], acc[mt][nt][1]);
            *(float2*)(C + (long long)(row + 8) * N + col) =
                make_float2(acc[mt][nt][2], acc[mt][nt][3]);
        }
    }

    // ---- softmax tile stats ----
    CP_WAIT(0);
    __syncthreads();
    float* smax = (float*)smem;
    float* ssum = (float*)(smem + 1024);

    float mrow[2][2];
#pragma unroll
    for (int mt = 0; mt < 2; mt++)
#pragma unroll
        for (int h = 0; h < 2; h++) {
            float m = -3.0e38f;
#pragma unroll
            for (int nt = 0; nt < 8; nt++)
                m = fmaxf(m, fmaxf(acc[mt][nt][2 * h], acc[mt][nt][2 * h + 1]));
            m = fmaxf(m, __shfl_xor_sync(0xffffffffu, m, 1));
            m = fmaxf(m, __shfl_xor_sync(0xffffffffu, m, 2));
            const int rloc = wm * 32 + mt * 16 + h * 8 + (lid >> 2);
            if ((lid & 3) == 0) smax[wn * 128 + rloc] = m;
        }
    __syncthreads();
#pragma unroll
    for (int mt = 0; mt < 2; mt++)
#pragma unroll
        for (int h = 0; h < 2; h++) {
            const int rloc = wm * 32 + mt * 16 + h * 8 + (lid >> 2);
            mrow[mt][h] = fmaxf(smax[rloc], smax[128 + rloc]);
            float s = 0.0f;
#pragma unroll
            for (int nt = 0; nt < 8; nt++)
                s += __expf(acc[mt][nt][2 * h] - mrow[mt][h]) +
                     __expf(acc[mt][nt][2 * h + 1] - mrow[mt][h]);
            s += __shfl_xor_sync(0xffffffffu, s, 1);
            s += __shfl_xor_sync(0xffffffffu, s, 2);
            if ((lid & 3) == 0) ssum[wn * 128 + rloc] = s;
        }
    __syncthreads();
    if (wn == 0 && (lid & 3) == 0) {
#pragma unroll
        for (int mt = 0; mt < 2; mt++)
#pragma unroll
            for (int h = 0; h < 2; h++) {
                const int rloc = wm * 32 + mt * 16 + h * 8 + (lid >> 2);
                const long long row = (long long)blockIdx.z * TQ + m0 + rloc;
                stat[row * 16 + blockIdx.x] =
                    make_float2(mrow[mt][h], ssum[rloc] + ssum[128 + rloc]);
            }
    }
}

// ---------------------------------------------------------------------------
// Reduce 16 tile stats per row -> (rowmax, 1/rowsum)
// ---------------------------------------------------------------------------
__global__ void __launch_bounds__(256)
rowstat_kernel(const float2* __restrict__ stat, float2* __restrict__ rowinfo)
{
    const int idx = blockIdx.x * 256 + threadIdx.x;
    const float2* t = stat + (long long)idx * 16;
    float m = t[0].x;
#pragma unroll
    for (int i = 1; i < 16; i++) m = fmaxf(m, t[i].x);
    float s = 0.0f;
#pragma unroll
    for (int i = 0; i < 16; i++) s += t[i].y * __expf(t[i].x - m);
    rowinfo[idx] = make_float2(m, 1.0f / s);
}

// ===========================================================================
// GEMM2 (fused softmax): O = softmax(S) @ E.
// R14 layout/loaders verbatim; mainloop restructured kstep-major with
// FRAGMENT REUSE across the 3 split sub-passes:
//   per 16-k step: ld A_hi,B_hi -> 8 MMA hi*hi
//                  ld A_lo      -> 8 MMA lo*hi (B_hi reused)
//                  ld B_lo      -> 8 MMA hi*lo (A_hi reused)  + prefetch next hi
// LDSM per kstep 12 -> 8.
// ===========================================================================
#define ROWB2A 272                          // A row stride
#define ROWB2B 560                          // B row stride (512 data + 48 pad)
#define A2_ST  (64 * ROWB2A)                // 17408
#define B2_ST  (64 * ROWB2B)                // 35840
#define STG2   (A2_ST + B2_ST)              // 53248
#define GEMM2_SMEM (2 * STG2)               // 106496

__global__ void __launch_bounds__(256, 2)
gemm2_fused(const float* __restrict__ S, const __nv_bfloat16* __restrict__ E2,
            const float2* __restrict__ rowinfo, float* __restrict__ O)
{
    extern __shared__ char smem[];
    const u32 smem_base = smem_u32(smem);

    constexpr int NC = TK / 64;   // 32 chunks

    const int tid = threadIdx.x;
    const int wid = tid >> 5;
    const int lid = tid & 31;
    const int wm  = wid & 1;      // 2 warps along M (32 rows)
    const int wn  = wid >> 1;     // 4 warps along N (32 cols)

    const int bz = blockIdx.z;
    const int m0 = blockIdx.y * 64;
    const int n0 = blockIdx.x * 128;

    // A loader: 4 threads per row, 16 fp32 each
    const int ar = tid >> 2;
    const int aq = tid & 3;
    const float* Ap = S + ((long long)bz * TQ + m0 + ar) * TK + aq * 16;
    const float2 ri = rowinfo[(long long)bz * TQ + m0 + ar];
    const float m_r = ri.x, inv_r = ri.y;

    // B loader: 4 threads per token row, 8 x 16B chunks each (32 per row)
    const int br = tid >> 2;
    const int bq = tid & 3;
    const __nv_bfloat16* Bp = E2 + ((long long)bz * TK + br) * (2 * DIM);

    // fragment addresses (within stage)
    const int a_base = (wm * 32 + (lid & 15)) * ROWB2A + ((lid >> 4) << 4);
    const int b_base = (lid & 15) * ROWB2B + ((lid >> 4) << 4) + wn * 64;

    float acc[2][4][4];
#pragma unroll
    for (int mt = 0; mt < 2; mt++)
#pragma unroll
        for (int nt = 0; nt < 4; nt++)
#pragma unroll
            for (int j = 0; j < 4; j++) acc[mt][nt][j] = 0.0f;

    float4 av[4];

    auto lda = [&](int c) {
#pragma unroll
        for (int i = 0; i < 4; i++) av[i] = *(const float4*)(Ap + c * 64 + i * 4);
    };
    auto ldb = [&](int st, int c) {
        const u32 sb = smem_base + st * STG2 + A2_ST;
        const __nv_bfloat16* src = Bp + (long long)c * 64 * (2 * DIM);
#pragma unroll
        for (int i = 0; i < 8; i++) {
            const int cc = bq + 4 * i;                       // 0..31
            const int go = (cc < 16) ? (n0 + cc * 8) : (DIM + n0 + (cc - 16) * 8);
            CP_ASYNC_16(sb + br * ROWB2B + cc * 16, src + go);
        }
    };
    auto cvta = [&](int st) {
        char* dst = smem + st * STG2 + ar * ROWB2A + aq * 32;
        u32 hi[8], lo[8];
        const float* f = (const float*)av;
#pragma unroll
        for (int j = 0; j < 8; j++) {
            const float p0 = __expf(f[2 * j]     - m_r) * inv_r;
            const float p1 = __expf(f[2 * j + 1] - m_r) * inv_r;
            const __nv_bfloat16 h0 = __float2bfloat16(p0);
            const __nv_bfloat16 h1 = __float2bfloat16(p1);
            const __nv_bfloat16 l0 = __float2bfloat16(p0 - __bfloat162float(h0));
            const __nv_bfloat16 l1 = __float2bfloat16(p1 - __bfloat162float(h1));
            __nv_bfloat162 hh, ll;
            hh.x = h0; hh.y = h1; ll.x = l0; ll.y = l1;
            hi[j] = *(u32*)&hh; lo[j] = *(u32*)&ll;
        }
        *(uint4*)(dst)            = make_uint4(hi[0], hi[1], hi[2], hi[3]);
        *(uint4*)(dst + 16)       = make_uint4(hi[4], hi[5], hi[6], hi[7]);
        *(uint4*)(dst + 128)      = make_uint4(lo[0], lo[1], lo[2], lo[3]);
        *(uint4*)(dst + 128 + 16) = make_uint4(lo[4], lo[5], lo[6], lo[7]);
    };

    lda(0);
    ldb(0, 0); CP_COMMIT();
    cvta(0);

    for (int c = 0; c < NC; c++) {
        CP_WAIT(0);
        __syncthreads();

        if (c + 1 < NC) {
            lda(c + 1);
            ldb((c + 1) & 1, c + 1);
            CP_COMMIT();
        }

        const u32 sa = smem_base + (c & 1) * STG2;
        const u32 sb = sa + A2_ST;

        u32 ah[2][2][4];   // A_hi fragments, dbuf x mt
        u32 bh[2][8];      // B_hi fragments, dbuf
        u32 al[2][4];      // A_lo (single buffer)
        u32 bl[8];         // B_lo (single buffer)

        // preload ks=0 hi fragments
        ldmatrix_x4(ah[0][0][0], ah[0][0][1], ah[0][0][2], ah[0][0][3], sa + a_base);
        ldmatrix_x4(ah[0][1][0], ah[0][1][1], ah[0][1][2], ah[0][1][3],
                    sa + a_base + 16 * ROWB2A);
        ldmatrix_x4_trans(bh[0][0], bh[0][1], bh[0][2], bh[0][3], sb + b_base);
        ldmatrix_x4_trans(bh[0][4], bh[0][5], bh[0][6], bh[0][7], sb + b_base + 32);

#pragma unroll
        for (int ks = 0; ks < 4; ks++) {
            const int cb = ks & 1, nb = cb ^ 1;
            const int aoff = ks * 32;
            const int boff = ks * 16 * ROWB2B;

            // phase 0: prefetch A_lo; MMA hi*hi
            ldmatrix_x4(al[0][0], al[0][1], al[0][2], al[0][3],
                        sa + a_base + 128 + aoff);
            ldmatrix_x4(al[1][0], al[1][1], al[1][2], al[1][3],
                        sa + a_base + 128 + aoff + 16 * ROWB2A);
#pragma unroll
            for (int mt = 0; mt < 2; mt++)
#pragma unroll
                for (int nt = 0; nt < 4; nt++)
                    mma_16816(acc[mt][nt], ah[cb][mt], &bh[cb][2 * nt]);

            // phase 1: prefetch B_lo; MMA lo*hi (reuse B_hi)
            ldmatrix_x4_trans(bl[0], bl[1], bl[2], bl[3],
                              sb + b_base + boff + 256);
            ldmatrix_x4_trans(bl[4], bl[5], bl[6], bl[7],
                              sb + b_base + boff + 256 + 32);
#pragma unroll
            for (int mt = 0; mt < 2; mt++)
#pragma unroll
                for (int nt = 0; nt < 4; nt++)
                    mma_16816(acc[mt][nt], al[mt], &bh[cb][2 * nt]);

            // phase 2: prefetch next-ks hi; MMA hi*lo (reuse A_hi)
            if (ks < 3) {
                ldmatrix_x4(ah[nb][0][0], ah[nb][0][1], ah[nb][0][2], ah[nb][0][3],
                            sa + a_base + aoff + 32);
                ldmatrix_x4(ah[nb][1][0], ah[nb][1][1], ah[nb][1][2], ah[nb][1][3],
                            sa + a_base + aoff + 32 + 16 * ROWB2A);
                ldmatrix_x4_trans(bh[nb][0], bh[nb][1], bh[nb][2], bh[nb][3],
                                  sb + b_base + boff + 16 * ROWB2B);
                ldmatrix_x4_trans(bh[nb][4], bh[nb][5], bh[nb][6], bh[nb][7],
                                  sb + b_base + boff + 16 * ROWB2B + 32);
            }
#pragma unroll
            for (int mt = 0; mt < 2; mt++)
#pragma unroll
                for (int nt = 0; nt < 4; nt++)
                    mma_16816(acc[mt][nt], ah[cb][mt], &bl[2 * nt]);
        }

        if (c + 1 < NC) cvta((c + 1) & 1);
    }

    // ---- epilogue: O f32 ----
    O += (long long)bz * TQ * DIM;
#pragma unroll
    for (int mt = 0; mt < 2; mt++) {
        const int row = m0 + wm * 32 + mt * 16 + (lid >> 2);
#pragma unroll
        for (int nt = 0; nt < 4; nt++) {
            const int col = n0 + wn * 32 + nt * 8 + ((lid & 3) << 1);
            *(float2*)(O + (long long)row * DIM + col) =
                make_float2(acc[mt][nt][0], acc[mt][nt][1]);
            *(float2*)(O + (long long)(row + 8) * DIM + col) =
                make_float2(acc[mt][nt][2], acc[mt][nt][3]);
        }
    }
}

// ---------------------------------------------------------------------------
// Row-wise hi/lo split (used for both Q and E)
// ---------------------------------------------------------------------------
template <int K>
__global__ void __launch_bounds__(256)
split2_kernel(const float* __restrict__ in, __nv_bfloat16* __restrict__ out,
              long long total)
{
    const long long n4 = total >> 2;
    for (long long i = (long long)blockIdx.x * blockDim.x + threadIdx.x;
         i < n4; i += (long long)gridDim.x * blockDim.x) {
        const long long e = i << 2;
        const long long r = e / K;
        const int k = (int)(e - r * (long long)K);
        const float4 x = *(const float4*)(in + e);
        const float xs[4] = {x.x, x.y, x.z, x.w};
        __nv_bfloat16 h[4], l[4];
#pragma unroll
        for (int j = 0; j < 4; j++) {
            h[j] = __float2bfloat16(xs[j]);
            l[j] = __float2bfloat16(xs[j] - __bfloat162float(h[j]));
        }
        __nv_bfloat16* o = out + r * (2LL * K) + k;
        __nv_bfloat162 hh0, hh1, ll0, ll1;
        hh0.x = h[0]; hh0.y = h[1]; hh1.x = h[2]; hh1.y = h[3];
        ll0.x = l[0]; ll0.y = l[1]; ll1.x = l[2]; ll1.y = l[3];
        *(__nv_bfloat162*)(o + 0)     = hh0;
        *(__nv_bfloat162*)(o + 2)     = hh1;
        *(__nv_bfloat162*)(o + K)     = ll0;
        *(__nv_bfloat162*)(o + K + 2) = ll1;
    }
}

// ---------------------------------------------------------------------------
// Entry point
// ---------------------------------------------------------------------------
extern "C" void kernel_launch(void* const* d_in, const int* in_sizes, int n_in,
                              void* d_out, int out_size)
{
    const float* Q = (const float*)d_in[0];
    const float* E = (const float*)d_in[1];
    float* O = (float*)d_out;

    __nv_bfloat16 *Q2, *E2;
    float* S;
    float2 *stat, *rowi;
    cudaGetSymbolAddress((void**)&Q2,   g_Q2);
    cudaGetSymbolAddress((void**)&E2,   g_E2);
    cudaGetSymbolAddress((void**)&S,    g_S);
    cudaGetSymbolAddress((void**)&stat, g_stat);
    cudaGetSymbolAddress((void**)&rowi, g_row);

    cudaFuncSetAttribute(gemm1_stats, cudaFuncAttributeMaxDynamicSharedMemorySize, GEMM_SMEM);
    cudaFuncSetAttribute(gemm2_fused, cudaFuncAttributeMaxDynamicSharedMemorySize, GEMM2_SMEM);

    // operand conversions
    split2_kernel<DIM><<<8192, 256>>>(Q, Q2, (long long)BATCH * TQ * DIM);
    split2_kernel<DIM><<<32768, 256>>>(E, E2, (long long)BATCH * TK * DIM);

    // S = Q @ E^T  + per-tile softmax stats
    gemm1_stats<<<dim3(TK / 128, TQ / 128, BATCH), 256, GEMM_SMEM>>>(Q2, E2, S, stat);

    // merge tile stats -> per-row (max, 1/sum)
    rowstat_kernel<<<BATCH * TQ / 256, 256>>>(stat, rowi);

    // O = softmax(S) @ E  (fused exp/normalize/split; fragment-reuse mainloop)
    gemm2_fused<<<dim3(DIM / 128, TQ / 64, BATCH), 256, GEMM2_SMEM>>>(S, E2, rowi, O);
}

// round 16
// speedup vs baseline: 1.1804x; 1.0207x over previous
#include <cuda_runtime.h>
#include <cuda_bf16.h>

typedef unsigned int       u32;
typedef unsigned long long u64;

#define BATCH 32
#define TQ    512
#define TK    2048
#define DIM   512

// ---------------------------------------------------------------------------
// Scratch. 2-section split storage: row = [hi(K) | lo(K)].
// Product = hi*hi + lo*hi + hi*lo (fp32 minus O(2^-18) lo*lo term)
// ---------------------------------------------------------------------------
__device__ __nv_bfloat16 g_Q2 [(size_t)BATCH * TQ  * 2 * DIM];  //  34 MB
__device__ __nv_bfloat16 g_E2 [(size_t)BATCH * TK  * 2 * DIM];  // 134 MB
__device__ float         g_S  [(size_t)BATCH * TQ  * TK];       // 134 MB
__device__ float2        g_stat[(size_t)BATCH * TQ * (TK / 128)]; // 2 MB
__device__ float2        g_row [(size_t)BATCH * TQ];              // 128 KB

// ---------------------------------------------------------------------------
// Baseline-PTX tensor-core helpers
// ---------------------------------------------------------------------------
__device__ __forceinline__ u32 smem_u32(const void* p) {
    u32 a;
    asm("{ .reg .u64 t; cvta.to.shared.u64 t, %1; cvt.u32.u64 %0, t; }"
        : "=r"(a) : "l"(p));
    return a;
}

__device__ __forceinline__ void ldmatrix_x4(u32& r0, u32& r1, u32& r2, u32& r3,
                                            u32 addr) {
    asm volatile("ldmatrix.sync.aligned.m8n8.x4.shared.b16 {%0,%1,%2,%3}, [%4];"
                 : "=r"(r0), "=r"(r1), "=r"(r2), "=r"(r3) : "r"(addr));
}

__device__ __forceinline__ void ldmatrix_x4_trans(u32& r0, u32& r1, u32& r2, u32& r3,
                                                  u32 addr) {
    asm volatile("ldmatrix.sync.aligned.m8n8.x4.trans.shared.b16 {%0,%1,%2,%3}, [%4];"
                 : "=r"(r0), "=r"(r1), "=r"(r2), "=r"(r3) : "r"(addr));
}

__device__ __forceinline__ void mma_16816(float* c, const u32* a, const u32* b) {
    asm volatile(
        "mma.sync.aligned.m16n8k16.row.col.f32.bf16.bf16.f32 "
        "{%0,%1,%2,%3}, {%4,%5,%6,%7}, {%8,%9}, {%0,%1,%2,%3};"
        : "+f"(c[0]), "+f"(c[1]), "+f"(c[2]), "+f"(c[3])
        : "r"(a[0]), "r"(a[1]), "r"(a[2]), "r"(a[3]), "r"(b[0]), "r"(b[1]));
}

#define CP_ASYNC_16(saddr, gptr) \
    asm volatile("cp.async.cg.shared.global [%0], [%1], 16;" \
                 :: "r"(saddr), "l"(gptr) : "memory")
#define CP_COMMIT() asm volatile("cp.async.commit_group;" ::: "memory")
#define CP_WAIT(n)  asm volatile("cp.async.wait_group %0;" :: "n"(n) : "memory")

// ===========================================================================
// GEMM1 (chunk-major + TRUE fragment reuse): S = Q @ E^T + softmax tile stats.
// Each 32-k chunk row = [hi 64B | lo 64B]; per 16-kstep:
//   ld A_hi,B_hi,A_lo -> 16 MMA hi*hi -> ld B_lo -> 16 MMA lo*hi (B_hi held)
//   -> 16 MMA hi*lo (A_hi held).
// LDSM:MMA 1:2.67 -> 1:4; gmem traffic -33%; barriers 24 -> 16.
// CTA 128x128, 3-stage cp.async, 8 warps (32m x 64n warp tiles).
// ===========================================================================
#define STAGES     3
#define ROWB       144
#define TILE_BYTES (128 * ROWB)
#define STAGE_BYTES (2 * TILE_BYTES)
#define GEMM_SMEM  (STAGES * STAGE_BYTES)    // 110592

__global__ void __launch_bounds__(256, 2)
gemm1_stats(const __nv_bfloat16* __restrict__ A, const __nv_bfloat16* __restrict__ B,
            float* __restrict__ C, float2* __restrict__ stat)
{
    extern __shared__ char smem[];
    const u32 smem_base = smem_u32(smem);

    constexpr int K   = DIM;
    constexpr int KT  = 2 * K;
    constexpr int NC  = K / 32;          // 16 chunks of 32k (hi+lo together)
    constexpr int N   = TK;

    const int tid = threadIdx.x;
    const int wid = tid >> 5;
    const int lid = tid & 31;
    const int wm  = wid & 3;
    const int wn  = wid >> 2;

    A += (long long)blockIdx.z * (TQ * (long long)KT);
    B += (long long)blockIdx.z * (TK * (long long)KT);
    C += (long long)blockIdx.z * ((long long)TQ * TK);
    const int m0 = blockIdx.y * 128;
    const int n0 = blockIdx.x * 128;

    // cp.async: q 0-3 -> hi 16B chunks, q 4-7 -> lo 16B chunks
    const int q  = tid & 7;
    const int r0 = tid >> 3;
    const int gcol = ((q < 4) ? 0 : K) + (q & 3) * 8;    // + c*32 at use

    const int a_off = (wm * 32 + (lid & 15)) * ROWB + ((lid >> 4) << 4);
    const int b_off = (wn * 64 + ((lid >> 4) << 3) + (lid & 7)) * ROWB +
                      (((lid >> 3) & 1) << 4);

    float acc[2][8][4];
#pragma unroll
    for (int mt = 0; mt < 2; mt++)
#pragma unroll
        for (int nt = 0; nt < 8; nt++)
#pragma unroll
            for (int j = 0; j < 4; j++) acc[mt][nt][j] = 0.0f;

    auto load_stage = [&](int s, int c) {
        const u32 sa = smem_base + s * STAGE_BYTES;
        const u32 sb = sa + TILE_BYTES;
        const __nv_bfloat16* Ap = A + (long long)(m0 + r0) * KT + gcol + c * 32;
        const __nv_bfloat16* Bp = B + (long long)(n0 + r0) * KT + gcol + c * 32;
#pragma unroll
        for (int i = 0; i < 4; i++) {
            CP_ASYNC_16(sa + (r0 + i * 32) * ROWB + q * 16, Ap + (long long)(i * 32) * KT);
            CP_ASYNC_16(sb + (r0 + i * 32) * ROWB + q * 16, Bp + (long long)(i * 32) * KT);
        }
    };

    load_stage(0, 0); CP_COMMIT();
    load_stage(1, 1); CP_COMMIT();

    int sc = 0, sl = 2;
    for (int c = 0; c < NC; c++) {
        CP_WAIT(1);
        __syncthreads();

        if (c + 2 < NC) load_stage(sl, c + 2);
        CP_COMMIT();

        const u32 sa = smem_base + sc * STAGE_BYTES;
        const u32 sb = sa + TILE_BYTES;

#pragma unroll
        for (int ks = 0; ks < 2; ks++) {
            const int ko = ks * 32;          // kstep byte offset within hi block

            u32 ah[2][4], al[2][4], bh[16], bl[16];

            // ---- load A_hi, B_hi ----
            ldmatrix_x4(ah[0][0], ah[0][1], ah[0][2], ah[0][3],
                        sa + a_off + ko);
            ldmatrix_x4(ah[1][0], ah[1][1], ah[1][2], ah[1][3],
                        sa + a_off + ko + 16 * ROWB);
#pragma unroll
            for (int bt = 0; bt < 4; bt++)
                ldmatrix_x4(bh[4 * bt], bh[4 * bt + 1], bh[4 * bt + 2], bh[4 * bt + 3],
                            sb + b_off + bt * 16 * ROWB + ko);

            // ---- load A_lo ----
            ldmatrix_x4(al[0][0], al[0][1], al[0][2], al[0][3],
                        sa + a_off + 64 + ko);
            ldmatrix_x4(al[1][0], al[1][1], al[1][2], al[1][3],
                        sa + a_off + 64 + ko + 16 * ROWB);

            // ---- MMA hi*hi ----
#pragma unroll
            for (int mt = 0; mt < 2; mt++)
#pragma unroll
                for (int nt = 0; nt < 8; nt++)
                    mma_16816(acc[mt][nt], ah[mt], &bh[2 * nt]);

            // ---- load B_lo ----
#pragma unroll
            for (int bt = 0; bt < 4; bt++)
                ldmatrix_x4(bl[4 * bt], bl[4 * bt + 1], bl[4 * bt + 2], bl[4 * bt + 3],
                            sb + b_off + bt * 16 * ROWB + 64 + ko);

            // ---- MMA lo*hi (B_hi reused) ----
#pragma unroll
            for (int mt = 0; mt < 2; mt++)
#pragma unroll
                for (int nt = 0; nt < 8; nt++)
                    mma_16816(acc[mt][nt], al[mt], &bh[2 * nt]);

            // ---- MMA hi*lo (A_hi reused) ----
#pragma unroll
            for (int mt = 0; mt < 2; mt++)
#pragma unroll
                for (int nt = 0; nt < 8; nt++)
                    mma_16816(acc[mt][nt], ah[mt], &bl[2 * nt]);
        }

        sc = (sc + 1 == STAGES) ? 0 : sc + 1;
        sl = (sl + 1 == STAGES) ? 0 : sl + 1;
    }

    // ---- store S ----
#pragma unroll
    for (int mt = 0; mt < 2; mt++) {
        const int row = m0 + wm * 32 + mt * 16 + (lid >> 2);
#pragma unroll
        for (int nt = 0; nt < 8; nt++) {
            const int col = n0 + wn * 64 + nt * 8 + ((lid & 3) << 1);
            *(float2*)(C + (long long)row * N + col) =
                make_float2(acc[mt][nt][0], acc[mt][nt][1]);
            *(float2*)(C + (long long)(row + 8) * N + col) =
                make_float2(acc[mt][nt][2], acc[mt][nt][3]);
        }
    }

    // ---- softmax tile stats ----
    CP_WAIT(0);
    __syncthreads();
    float* smax = (float*)smem;
    float* ssum = (float*)(smem + 1024);

    float mrow[2][2];
#pragma unroll
    for (int mt = 0; mt < 2; mt++)
#pragma unroll
        for (int h = 0; h < 2; h++) {
            float m = -3.0e38f;
#pragma unroll
            for (int nt = 0; nt < 8; nt++)
                m = fmaxf(m, fmaxf(acc[mt][nt][2 * h], acc[mt][nt][2 * h + 1]));
            m = fmaxf(m, __shfl_xor_sync(0xffffffffu, m, 1));
            m = fmaxf(m, __shfl_xor_sync(0xffffffffu, m, 2));
            const int rloc = wm * 32 + mt * 16 + h * 8 + (lid >> 2);
            if ((lid & 3) == 0) smax[wn * 128 + rloc] = m;
        }
    __syncthreads();
#pragma unroll
    for (int mt = 0; mt < 2; mt++)
#pragma unroll
        for (int h = 0; h < 2; h++) {
            const int rloc = wm * 32 + mt * 16 + h * 8 + (lid >> 2);
            mrow[mt][h] = fmaxf(smax[rloc], smax[128 + rloc]);
            float s = 0.0f;
#pragma unroll
            for (int nt = 0; nt < 8; nt++)
                s += __expf(acc[mt][nt][2 * h] - mrow[mt][h]) +
                     __expf(acc[mt][nt][2 * h + 1] - mrow[mt][h]);
            s += __shfl_xor_sync(0xffffffffu, s, 1);
            s += __shfl_xor_sync(0xffffffffu, s, 2);
            if ((lid & 3) == 0) ssum[wn * 128 + rloc] = s;
        }
    __syncthreads();
    if (wn == 0 && (lid & 3) == 0) {
#pragma unroll
        for (int mt = 0; mt < 2; mt++)
#pragma unroll
            for (int h = 0; h < 2; h++) {
                const int rloc = wm * 32 + mt * 16 + h * 8 + (lid >> 2);
                const long long row = (long long)blockIdx.z * TQ + m0 + rloc;
                stat[row * 16 + blockIdx.x] =
                    make_float2(mrow[mt][h], ssum[rloc] + ssum[128 + rloc]);
            }
    }
}

// ---------------------------------------------------------------------------
// Reduce 16 tile stats per row -> (rowmax, 1/rowsum)
// ---------------------------------------------------------------------------
__global__ void __launch_bounds__(256)
rowstat_kernel(const float2* __restrict__ stat, float2* __restrict__ rowinfo)
{
    const int idx = blockIdx.x * 256 + threadIdx.x;
    const float2* t = stat + (long long)idx * 16;
    float m = t[0].x;
#pragma unroll
    for (int i = 1; i < 16; i++) m = fmaxf(m, t[i].x);
    float s = 0.0f;
#pragma unroll
    for (int i = 0; i < 16; i++) s += t[i].y * __expf(t[i].x - m);
    rowinfo[idx] = make_float2(m, 1.0f / s);
}

// ===========================================================================
// GEMM2 (fused softmax): O = softmax(S) @ E.  (R15 kernel, verbatim.)
// ===========================================================================
#define ROWB2A 272                          // A row stride
#define ROWB2B 560                          // B row stride (512 data + 48 pad)
#define A2_ST  (64 * ROWB2A)                // 17408
#define B2_ST  (64 * ROWB2B)                // 35840
#define STG2   (A2_ST + B2_ST)              // 53248
#define GEMM2_SMEM (2 * STG2)               // 106496

__global__ void __launch_bounds__(256, 2)
gemm2_fused(const float* __restrict__ S, const __nv_bfloat16* __restrict__ E2,
            const float2* __restrict__ rowinfo, float* __restrict__ O)
{
    extern __shared__ char smem[];
    const u32 smem_base = smem_u32(smem);

    constexpr int NC = TK / 64;   // 32 chunks

    const int tid = threadIdx.x;
    const int wid = tid >> 5;
    const int lid = tid & 31;
    const int wm  = wid & 1;      // 2 warps along M (32 rows)
    const int wn  = wid >> 1;     // 4 warps along N (32 cols)

    const int bz = blockIdx.z;
    const int m0 = blockIdx.y * 64;
    const int n0 = blockIdx.x * 128;

    const int ar = tid >> 2;
    const int aq = tid & 3;
    const float* Ap = S + ((long long)bz * TQ + m0 + ar) * TK + aq * 16;
    const float2 ri = rowinfo[(long long)bz * TQ + m0 + ar];
    const float m_r = ri.x, inv_r = ri.y;

    const int br = tid >> 2;
    const int bq = tid & 3;
    const __nv_bfloat16* Bp = E2 + ((long long)bz * TK + br) * (2 * DIM);

    const int a_base = (wm * 32 + (lid & 15)) * ROWB2A + ((lid >> 4) << 4);
    const int b_base = (lid & 15) * ROWB2B + ((lid >> 4) << 4) + wn * 64;

    float acc[2][4][4];
#pragma unroll
    for (int mt = 0; mt < 2; mt++)
#pragma unroll
        for (int nt = 0; nt < 4; nt++)
#pragma unroll
            for (int j = 0; j < 4; j++) acc[mt][nt][j] = 0.0f;

    float4 av[4];

    auto lda = [&](int c) {
#pragma unroll
        for (int i = 0; i < 4; i++) av[i] = *(const float4*)(Ap + c * 64 + i * 4);
    };
    auto ldb = [&](int st, int c) {
        const u32 sb = smem_base + st * STG2 + A2_ST;
        const __nv_bfloat16* src = Bp + (long long)c * 64 * (2 * DIM);
#pragma unroll
        for (int i = 0; i < 8; i++) {
            const int cc = bq + 4 * i;
            const int go = (cc < 16) ? (n0 + cc * 8) : (DIM + n0 + (cc - 16) * 8);
            CP_ASYNC_16(sb + br * ROWB2B + cc * 16, src + go);
        }
    };
    auto cvta = [&](int st) {
        char* dst = smem + st * STG2 + ar * ROWB2A + aq * 32;
        u32 hi[8], lo[8];
        const float* f = (const float*)av;
#pragma unroll
        for (int j = 0; j < 8; j++) {
            const float p0 = __expf(f[2 * j]     - m_r) * inv_r;
            const float p1 = __expf(f[2 * j + 1] - m_r) * inv_r;
            const __nv_bfloat16 h0 = __float2bfloat16(p0);
            const __nv_bfloat16 h1 = __float2bfloat16(p1);
            const __nv_bfloat16 l0 = __float2bfloat16(p0 - __bfloat162float(h0));
            const __nv_bfloat16 l1 = __float2bfloat16(p1 - __bfloat162float(h1));
            __nv_bfloat162 hh, ll;
            hh.x = h0; hh.y = h1; ll.x = l0; ll.y = l1;
            hi[j] = *(u32*)&hh; lo[j] = *(u32*)&ll;
        }
        *(uint4*)(dst)            = make_uint4(hi[0], hi[1], hi[2], hi[3]);
        *(uint4*)(dst + 16)       = make_uint4(hi[4], hi[5], hi[6], hi[7]);
        *(uint4*)(dst + 128)      = make_uint4(lo[0], lo[1], lo[2], lo[3]);
        *(uint4*)(dst + 128 + 16) = make_uint4(lo[4], lo[5], lo[6], lo[7]);
    };

    lda(0);
    ldb(0, 0); CP_COMMIT();
    cvta(0);

    for (int c = 0; c < NC; c++) {
        CP_WAIT(0);
        __syncthreads();

        if (c + 1 < NC) {
            lda(c + 1);
            ldb((c + 1) & 1, c + 1);
            CP_COMMIT();
        }

        const u32 sa = smem_base + (c & 1) * STG2;
        const u32 sb = sa + A2_ST;

        u32 ah[2][2][4];
        u32 bh[2][8];
        u32 al[2][4];
        u32 bl[8];

        ldmatrix_x4(ah[0][0][0], ah[0][0][1], ah[0][0][2], ah[0][0][3], sa + a_base);
        ldmatrix_x4(ah[0][1][0], ah[0][1][1], ah[0][1][2], ah[0][1][3],
                    sa + a_base + 16 * ROWB2A);
        ldmatrix_x4_trans(bh[0][0], bh[0][1], bh[0][2], bh[0][3], sb + b_base);
        ldmatrix_x4_trans(bh[0][4], bh[0][5], bh[0][6], bh[0][7], sb + b_base + 32);

#pragma unroll
        for (int ks = 0; ks < 4; ks++) {
            const int cb = ks & 1, nb = cb ^ 1;
            const int aoff = ks * 32;
            const int boff = ks * 16 * ROWB2B;

            ldmatrix_x4(al[0][0], al[0][1], al[0][2], al[0][3],
                        sa + a_base + 128 + aoff);
            ldmatrix_x4(al[1][0], al[1][1], al[1][2], al[1][3],
                        sa + a_base + 128 + aoff + 16 * ROWB2A);
#pragma unroll
            for (int mt = 0; mt < 2; mt++)
#pragma unroll
                for (int nt = 0; nt < 4; nt++)
                    mma_16816(acc[mt][nt], ah[cb][mt], &bh[cb][2 * nt]);

            ldmatrix_x4_trans(bl[0], bl[1], bl[2], bl[3],
                              sb + b_base + boff + 256);
            ldmatrix_x4_trans(bl[4], bl[5], bl[6], bl[7],
                              sb + b_base + boff + 256 + 32);
#pragma unroll
            for (int mt = 0; mt < 2; mt++)
#pragma unroll
                for (int nt = 0; nt < 4; nt++)
                    mma_16816(acc[mt][nt], al[mt], &bh[cb][2 * nt]);

            if (ks < 3) {
                ldmatrix_x4(ah[nb][0][0], ah[nb][0][1], ah[nb][0][2], ah[nb][0][3],
                            sa + a_base + aoff + 32);
                ldmatrix_x4(ah[nb][1][0], ah[nb][1][1], ah[nb][1][2], ah[nb][1][3],
                            sa + a_base + aoff + 32 + 16 * ROWB2A);
                ldmatrix_x4_trans(bh[nb][0], bh[nb][1], bh[nb][2], bh[nb][3],
                                  sb + b_base + boff + 16 * ROWB2B);
                ldmatrix_x4_trans(bh[nb][4], bh[nb][5], bh[nb][6], bh[nb][7],
                                  sb + b_base + boff + 16 * ROWB2B + 32);
            }
#pragma unroll
            for (int mt = 0; mt < 2; mt++)
#pragma unroll
                for (int nt = 0; nt < 4; nt++)
                    mma_16816(acc[mt][nt], ah[cb][mt], &bl[2 * nt]);
        }

        if (c + 1 < NC) cvta((c + 1) & 1);
    }

    O += (long long)bz * TQ * DIM;
#pragma unroll
    for (int mt = 0; mt < 2; mt++) {
        const int row = m0 + wm * 32 + mt * 16 + (lid >> 2);
#pragma unroll
        for (int nt = 0; nt < 4; nt++) {
            const int col = n0 + wn * 32 + nt * 8 + ((lid & 3) << 1);
            *(float2*)(O + (long long)row * DIM + col) =
                make_float2(acc[mt][nt][0], acc[mt][nt][1]);
            *(float2*)(O + (long long)(row + 8) * DIM + col) =
                make_float2(acc[mt][nt][2], acc[mt][nt][3]);
        }
    }
}

// ---------------------------------------------------------------------------
// Row-wise hi/lo split (used for both Q and E)
// ---------------------------------------------------------------------------
template <int K>
__global__ void __launch_bounds__(256)
split2_kernel(const float* __restrict__ in, __nv_bfloat16* __restrict__ out,
              long long total)
{
    const long long n4 = total >> 2;
    for (long long i = (long long)blockIdx.x * blockDim.x + threadIdx.x;
         i < n4; i += (long long)gridDim.x * blockDim.x) {
        const long long e = i << 2;
        const long long r = e / K;
        const int k = (int)(e - r * (long long)K);
        const float4 x = *(const float4*)(in + e);
        const float xs[4] = {x.x, x.y, x.z, x.w};
        __nv_bfloat16 h[4], l[4];
#pragma unroll
        for (int j = 0; j < 4; j++) {
            h[j] = __float2bfloat16(xs[j]);
            l[j] = __float2bfloat16(xs[j] - __bfloat162float(h[j]));
        }
        __nv_bfloat16* o = out + r * (2LL * K) + k;
        __nv_bfloat162 hh0, hh1, ll0, ll1;
        hh0.x = h[0]; hh0.y = h[1]; hh1.x = h[2]; hh1.y = h[3];
        ll0.x = l[0]; ll0.y = l[1]; ll1.x = l[2]; ll1.y = l[3];
        *(__nv_bfloat162*)(o + 0)     = hh0;
        *(__nv_bfloat162*)(o + 2)     = hh1;
        *(__nv_bfloat162*)(o + K)     = ll0;
        *(__nv_bfloat162*)(o + K + 2) = ll1;
    }
}

// ---------------------------------------------------------------------------
// Entry point
// ---------------------------------------------------------------------------
extern "C" void kernel_launch(void* const* d_in, const int* in_sizes, int n_in,
                              void* d_out, int out_size)
{
    const float* Q = (const float*)d_in[0];
    const float* E = (const float*)d_in[1];
    float* O = (float*)d_out;

    __nv_bfloat16 *Q2, *E2;
    float* S;
    float2 *stat, *rowi;
    cudaGetSymbolAddress((void**)&Q2,   g_Q2);
    cudaGetSymbolAddress((void**)&E2,   g_E2);
    cudaGetSymbolAddress((void**)&S,    g_S);
    cudaGetSymbolAddress((void**)&stat, g_stat);
    cudaGetSymbolAddress((void**)&rowi, g_row);

    cudaFuncSetAttribute(gemm1_stats, cudaFuncAttributeMaxDynamicSharedMemorySize, GEMM_SMEM);
    cudaFuncSetAttribute(gemm2_fused, cudaFuncAttributeMaxDynamicSharedMemorySize, GEMM2_SMEM);

    // operand conversions
    split2_kernel<DIM><<<8192, 256>>>(Q, Q2, (long long)BATCH * TQ * DIM);
    split2_kernel<DIM><<<32768, 256>>>(E, E2, (long long)BATCH * TK * DIM);

    // S = Q @ E^T  + per-tile softmax stats (fragment-reuse mainloop)
    gemm1_stats<<<dim3(TK / 128, TQ / 128, BATCH), 256, GEMM_SMEM>>>(Q2, E2, S, stat);

    // merge tile stats -> per-row (max, 1/sum)
    rowstat_kernel<<<BATCH * TQ / 256, 256>>>(stat, rowi);

    // O = softmax(S) @ E  (fused exp/normalize/split; fragment-reuse mainloop)
    gemm2_fused<<<dim3(DIM / 128, TQ / 64, BATCH), 256, GEMM2_SMEM>>>(S, E2, rowi, O);
}